// round 3
// baseline (speedup 1.0000x reference)
#include <cuda_runtime.h>
#include <cuda_bf16.h>

// Problem constants
constexpr int B_ = 2, N_ = 2048, E_ = 1024, H_ = 16, D_ = 64;
constexpr int BH = B_ * H_;          // 32

// Scratch (device globals — no allocation allowed)
__device__ float g_qh[BH * N_ * D_];     // [b*H+h][n][d]
__device__ float g_kh[BH * N_ * D_];
__device__ float g_vh[BH * N_ * D_];
__device__ float g_attn[B_ * N_ * E_];   // [b][n][h*64+d]

// ---------------------------------------------------------------------------
// Kernel 1: per-head linear projections  out[n][e'] = sum_d x[n][d] * W[h][e'][d]
// grid: (N/64, B*H, 3{q,k,v}), block 256
// ---------------------------------------------------------------------------
__global__ __launch_bounds__(256) void proj_kernel(
    const float* __restrict__ Q, const float* __restrict__ K, const float* __restrict__ V,
    const float* __restrict__ Wq, const float* __restrict__ Wk, const float* __restrict__ Wv)
{
    __shared__ __align__(16) float xs[64 * 68];   // x tile, padded rows
    __shared__ __align__(16) float wt[64 * 64];   // W transposed: wt[d][c]

    int which = blockIdx.z;
    const float* X = (which == 0) ? Q : (which == 1) ? K : V;
    const float* W = (which == 0) ? Wq : (which == 1) ? Wk : Wv;
    float* out = (which == 0) ? g_qh : (which == 1) ? g_kh : g_vh;

    int bh = blockIdx.y, b = bh >> 4, h = bh & 15;
    int n0 = blockIdx.x * 64;
    int t = threadIdx.x;

    // load W[h] (64x64, row-major e',d) transposed into smem
    for (int i = t; i < 4096; i += 256) {
        int c = i >> 6, d = i & 63;
        wt[d * 64 + c] = W[h * 4096 + i];
    }
    // load X tile: rows n0..n0+63, cols h*64..h*64+63
    const float* Xb = X + ((size_t)b * N_ + n0) * E_ + h * 64;
    for (int idx = t; idx < 1024; idx += 256) {
        int r = idx >> 4, d4 = (idx & 15) * 4;
        *(float4*)&xs[r * 68 + d4] = *(const float4*)&Xb[(size_t)r * E_ + d4];
    }
    __syncthreads();

    int r0 = (t >> 4) * 4, c0 = (t & 15) * 4;
    float acc[4][4] = {};
    #pragma unroll 16
    for (int d = 0; d < 64; d++) {
        float4 wv = *(float4*)&wt[d * 64 + c0];
        #pragma unroll
        for (int i = 0; i < 4; i++) {
            float xv = xs[(r0 + i) * 68 + d];
            acc[i][0] += xv * wv.x; acc[i][1] += xv * wv.y;
            acc[i][2] += xv * wv.z; acc[i][3] += xv * wv.w;
        }
    }
    float* ob = out + ((size_t)bh * N_ + n0) * 64;
    #pragma unroll
    for (int i = 0; i < 4; i++) {
        float4 o = make_float4(acc[i][0], acc[i][1], acc[i][2], acc[i][3]);
        *(float4*)&ob[(r0 + i) * 64 + c0] = o;
    }
}

// ---------------------------------------------------------------------------
// Kernel 2: flash attention per (b,h) with 64-row Q tiles, online softmax.
// Masked query rows: all scores := 0  (softmax of a constant == uniform, which
// is exactly what the reference's -1e28 row-mask produces).
// grid: (N/64, B*H), block 256, dynamic smem ~70KB
// ---------------------------------------------------------------------------
__global__ __launch_bounds__(256) void attn_kernel(const int* __restrict__ mask)
{
    extern __shared__ __align__(16) float sm[];
    float* Qs = sm;                 // 64x68
    float* Ks = Qs + 64 * 68;
    float* Vs = Ks + 64 * 68;
    float* Ss = Vs + 64 * 68;       // raw scores, then P
    float* frow = Ss + 64 * 68;     // [64] rescale factors
    float* lrow = frow + 64;        // [64] final denominators
    int*   mrow = (int*)(lrow + 64);// [64] mask flags

    int bh = blockIdx.y, b = bh >> 4, h = bh & 15;
    int q0 = blockIdx.x * 64;
    int t = threadIdx.x;

    const float* Qg = g_qh + ((size_t)bh * N_ + q0) * 64;
    const float* Kg = g_kh + (size_t)bh * N_ * 64;
    const float* Vg = g_vh + (size_t)bh * N_ * 64;

    const float scale = 0.03125f;   // 1/sqrt(E) = 1/32, folded into Q
    for (int idx = t; idx < 1024; idx += 256) {
        int r = idx >> 4, d4 = (idx & 15) * 4;
        float4 qv = *(const float4*)&Qg[r * 64 + d4];
        qv.x *= scale; qv.y *= scale; qv.z *= scale; qv.w *= scale;
        *(float4*)&Qs[r * 68 + d4] = qv;
    }
    if (t < 64) mrow[t] = mask[b * N_ + q0 + t];

    // row-mapped view (softmax): thread owns row sr, k-cols sk0..sk0+15
    int sr = t >> 2, sk0 = (t & 3) * 16;
    float m = -1e30f, l = 0.f;
    // tile-mapped view (S compute / PV): 4 rows x 4 cols
    int r0 = (t >> 4) * 4, c0 = (t & 15) * 4;
    float acc[4][4] = {};

    for (int kt = 0; kt < N_ / 64; kt++) {
        __syncthreads();
        const float* kg = Kg + kt * 64 * 64;
        const float* vg = Vg + kt * 64 * 64;
        for (int idx = t; idx < 1024; idx += 256) {
            int r = idx >> 4, d4 = (idx & 15) * 4;
            *(float4*)&Ks[r * 68 + d4] = *(const float4*)&kg[r * 64 + d4];
            *(float4*)&Vs[r * 68 + d4] = *(const float4*)&vg[r * 64 + d4];
        }
        __syncthreads();

        // S = (Q/32) K^T, 4x4 register tile, float4 over d
        float s[4][4] = {};
        #pragma unroll
        for (int d4 = 0; d4 < 16; d4++) {
            float4 k4[4];
            #pragma unroll
            for (int j = 0; j < 4; j++) k4[j] = *(float4*)&Ks[(c0 + j) * 68 + d4 * 4];
            #pragma unroll
            for (int i = 0; i < 4; i++) {
                float4 q4 = *(float4*)&Qs[(r0 + i) * 68 + d4 * 4];
                #pragma unroll
                for (int j = 0; j < 4; j++)
                    s[i][j] += q4.x * k4[j].x + q4.y * k4[j].y + q4.z * k4[j].z + q4.w * k4[j].w;
            }
        }
        #pragma unroll
        for (int i = 0; i < 4; i++) {
            bool ok = (mrow[r0 + i] != 0);
            #pragma unroll
            for (int j = 0; j < 4; j++)
                Ss[(r0 + i) * 68 + c0 + j] = ok ? s[i][j] : 0.f;
        }
        __syncthreads();

        // online softmax (row view); 4 lanes per row combine via shfl
        float sv[16], mt = -1e30f;
        #pragma unroll
        for (int j = 0; j < 16; j++) { sv[j] = Ss[sr * 68 + sk0 + j]; mt = fmaxf(mt, sv[j]); }
        mt = fmaxf(mt, __shfl_xor_sync(0xffffffffu, mt, 1));
        mt = fmaxf(mt, __shfl_xor_sync(0xffffffffu, mt, 2));
        float mn = fmaxf(m, mt);
        float fac = __expf(m - mn);
        float ps = 0.f;
        #pragma unroll
        for (int j = 0; j < 16; j++) {
            float p = __expf(sv[j] - mn);
            ps += p;
            Ss[sr * 68 + sk0 + j] = p;     // overwrite S with P
        }
        ps += __shfl_xor_sync(0xffffffffu, ps, 1);
        ps += __shfl_xor_sync(0xffffffffu, ps, 2);
        l = l * fac + ps;
        m = mn;
        if ((t & 3) == 0) frow[sr] = fac;
        __syncthreads();

        // O = O*fac + P @ V  (tile view)
        #pragma unroll
        for (int i = 0; i < 4; i++) {
            float f = frow[r0 + i];
            #pragma unroll
            for (int j = 0; j < 4; j++) acc[i][j] *= f;
        }
        #pragma unroll 8
        for (int k = 0; k < 64; k++) {
            float4 v4 = *(float4*)&Vs[k * 68 + c0];
            #pragma unroll
            for (int i = 0; i < 4; i++) {
                float p = Ss[(r0 + i) * 68 + k];
                acc[i][0] += p * v4.x; acc[i][1] += p * v4.y;
                acc[i][2] += p * v4.z; acc[i][3] += p * v4.w;
            }
        }
    }
    if ((t & 3) == 0) lrow[sr] = l;
    __syncthreads();

    float* ob = g_attn + ((size_t)b * N_ + q0) * E_ + h * 64;
    #pragma unroll
    for (int i = 0; i < 4; i++) {
        float inv = 1.f / lrow[r0 + i];
        float4 o = make_float4(acc[i][0] * inv, acc[i][1] * inv, acc[i][2] * inv, acc[i][3] * inv);
        *(float4*)&ob[(size_t)(r0 + i) * E_ + c0] = o;
    }
}

// ---------------------------------------------------------------------------
// Kernel 3: out = attn @ Wo^T    (4096x1024) x (1024x1024)
// grid: (B*N/64, E/64), block 256
// ---------------------------------------------------------------------------
__global__ __launch_bounds__(256) void oproj_kernel(
    const float* __restrict__ Wo, float* __restrict__ out)
{
    __shared__ __align__(16) float As[64 * 68];
    __shared__ __align__(16) float Bs[64 * 68];
    int rB = blockIdx.x * 64, cB = blockIdx.y * 64;
    int t = threadIdx.x;
    int r0 = (t >> 4) * 4, c0 = (t & 15) * 4;
    float acc[4][4] = {};

    for (int e0 = 0; e0 < E_; e0 += 64) {
        __syncthreads();
        for (int idx = t; idx < 1024; idx += 256) {
            int r = idx >> 4, d4 = (idx & 15) * 4;
            *(float4*)&As[r * 68 + d4] = *(const float4*)&g_attn[(size_t)(rB + r) * E_ + e0 + d4];
            *(float4*)&Bs[r * 68 + d4] = *(const float4*)&Wo[(size_t)(cB + r) * E_ + e0 + d4];
        }
        __syncthreads();
        #pragma unroll
        for (int d4 = 0; d4 < 16; d4++) {
            float4 b4[4];
            #pragma unroll
            for (int j = 0; j < 4; j++) b4[j] = *(float4*)&Bs[(c0 + j) * 68 + d4 * 4];
            #pragma unroll
            for (int i = 0; i < 4; i++) {
                float4 a4 = *(float4*)&As[(r0 + i) * 68 + d4 * 4];
                #pragma unroll
                for (int j = 0; j < 4; j++)
                    acc[i][j] += a4.x * b4[j].x + a4.y * b4[j].y + a4.z * b4[j].z + a4.w * b4[j].w;
            }
        }
    }
    #pragma unroll
    for (int i = 0; i < 4; i++) {
        float4 o = make_float4(acc[i][0], acc[i][1], acc[i][2], acc[i][3]);
        *(float4*)&out[(size_t)(rB + r0 + i) * E_ + cB + c0] = o;
    }
}

// ---------------------------------------------------------------------------
extern "C" void kernel_launch(void* const* d_in, const int* in_sizes, int n_in,
                              void* d_out, int out_size)
{
    const float* q    = (const float*)d_in[0];
    const float* k    = (const float*)d_in[1];
    const float* v    = (const float*)d_in[2];
    const int*   mask = (const int*)  d_in[3];
    const float* Wq   = (const float*)d_in[4];
    const float* Wk   = (const float*)d_in[5];
    const float* Wv   = (const float*)d_in[6];
    const float* Wo   = (const float*)d_in[7];
    float* out = (float*)d_out;

    proj_kernel<<<dim3(N_ / 64, BH, 3), 256>>>(q, k, v, Wq, Wk, Wv);

    size_t smem = (4 * 64 * 68 + 3 * 64) * sizeof(float);   // ~70.4 KB
    cudaFuncSetAttribute(attn_kernel, cudaFuncAttributeMaxDynamicSharedMemorySize, (int)smem);
    attn_kernel<<<dim3(N_ / 64, BH), 256, smem>>>(mask);

    oproj_kernel<<<dim3(B_ * N_ / 64, E_ / 64), 256>>>(Wo, out);
}

// round 4
// speedup vs baseline: 4.5124x; 4.5124x over previous
#include <cuda_runtime.h>
#include <cuda_bf16.h>
#include <cstdint>

// Problem constants
constexpr int B_ = 2, N_ = 2048, E_ = 1024, H_ = 16, D_ = 64;
constexpr int BH = B_ * H_;          // 32

// Scratch (device globals — no allocation allowed)
__device__ float g_qh[BH * N_ * D_];     // [b*H+h][n][d]
__device__ float g_kh[BH * N_ * D_];
__device__ float g_vh[BH * N_ * D_];
__device__ float g_attn[B_ * N_ * E_];   // [b][n][h*64+d]

// ---------------------------------------------------------------------------
// tf32 helpers
// ---------------------------------------------------------------------------
__device__ __forceinline__ float f2tf(float x) {
    uint32_t r;
    asm("cvt.rna.tf32.f32 %0, %1;" : "=r"(r) : "f"(x));
    return __uint_as_float(r);
}
__device__ __forceinline__ void mma_tf32(float c[4],
    uint32_t a0, uint32_t a1, uint32_t a2, uint32_t a3,
    uint32_t b0, uint32_t b1)
{
    asm volatile(
        "mma.sync.aligned.m16n8k8.row.col.f32.tf32.tf32.f32 "
        "{%0,%1,%2,%3}, {%4,%5,%6,%7}, {%8,%9}, {%0,%1,%2,%3};"
        : "+f"(c[0]), "+f"(c[1]), "+f"(c[2]), "+f"(c[3])
        : "r"(a0), "r"(a1), "r"(a2), "r"(a3), "r"(b0), "r"(b1));
}

// ---------------------------------------------------------------------------
// Kernel 1: per-head linear projections (unchanged, 88us)
// ---------------------------------------------------------------------------
__global__ __launch_bounds__(256) void proj_kernel(
    const float* __restrict__ Q, const float* __restrict__ K, const float* __restrict__ V,
    const float* __restrict__ Wq, const float* __restrict__ Wk, const float* __restrict__ Wv)
{
    __shared__ __align__(16) float xs[64 * 68];
    __shared__ __align__(16) float wt[64 * 64];

    int which = blockIdx.z;
    const float* X = (which == 0) ? Q : (which == 1) ? K : V;
    const float* W = (which == 0) ? Wq : (which == 1) ? Wk : Wv;
    float* out = (which == 0) ? g_qh : (which == 1) ? g_kh : g_vh;

    int bh = blockIdx.y, b = bh >> 4, h = bh & 15;
    int n0 = blockIdx.x * 64;
    int t = threadIdx.x;

    for (int i = t; i < 4096; i += 256) {
        int c = i >> 6, d = i & 63;
        wt[d * 64 + c] = W[h * 4096 + i];
    }
    const float* Xb = X + ((size_t)b * N_ + n0) * E_ + h * 64;
    for (int idx = t; idx < 1024; idx += 256) {
        int r = idx >> 4, d4 = (idx & 15) * 4;
        *(float4*)&xs[r * 68 + d4] = *(const float4*)&Xb[(size_t)r * E_ + d4];
    }
    __syncthreads();

    int r0 = (t >> 4) * 4, c0 = (t & 15) * 4;
    float acc[4][4] = {};
    #pragma unroll 16
    for (int d = 0; d < 64; d++) {
        float4 wv = *(float4*)&wt[d * 64 + c0];
        #pragma unroll
        for (int i = 0; i < 4; i++) {
            float xv = xs[(r0 + i) * 68 + d];
            acc[i][0] += xv * wv.x; acc[i][1] += xv * wv.y;
            acc[i][2] += xv * wv.z; acc[i][3] += xv * wv.w;
        }
    }
    float* ob = out + ((size_t)bh * N_ + n0) * 64;
    #pragma unroll
    for (int i = 0; i < 4; i++) {
        float4 o = make_float4(acc[i][0], acc[i][1], acc[i][2], acc[i][3]);
        *(float4*)&ob[(r0 + i) * 64 + c0] = o;
    }
}

// ---------------------------------------------------------------------------
// Kernel 2: flash attention with tf32 mma.sync (m16n8k8).
// Block = 128 threads (4 warps). Each warp owns 16 query rows of a 64-row
// Q tile. Q fragments live in registers for the whole kernel. S fragments
// stay in registers; softmax runs on the C-fragment layout (2 rows/thread,
// shfl across the 4-lane group). P round-trips through a warp-private SMEM
// region to re-fragment for the PV mma (only __syncwarp needed).
// Masked query rows: scores := 0 (softmax of const row == uniform == reference).
// ---------------------------------------------------------------------------
__global__ __launch_bounds__(128) void attn_mma_kernel(const int* __restrict__ mask)
{
    __shared__ __align__(16) float Ks[64 * 68];   // [key][d], pad 68: 4g+tig conflict-free
    __shared__ __align__(16) float Vs[64 * 72];   // [key][d], pad 72: 8tig+g conflict-free
    __shared__ __align__(16) float Ps[64 * 68];   // P, rows partitioned per warp
    __shared__ int mrow[64];

    int bh = blockIdx.y, b = bh >> 4, h = bh & 15;
    int q0 = blockIdx.x * 64;
    int t = threadIdx.x;
    int w = t >> 5, lane = t & 31, g = lane >> 2, tig = lane & 3;

    const float* Qg = g_qh + ((size_t)bh * N_ + q0) * 64;
    const float* Kg = g_kh + (size_t)bh * N_ * 64;
    const float* Vg = g_vh + (size_t)bh * N_ * 64;

    if (t < 64) mrow[t] = mask[b * N_ + q0 + t];

    // Q fragments (tf32, scaled by 1/sqrt(E) = 1/32), kept for all K tiles
    int r_lo = w * 16 + g, r_hi = r_lo + 8;
    const float scale = 0.03125f;
    uint32_t qa[8][4];
    #pragma unroll
    for (int kk = 0; kk < 8; kk++) {
        qa[kk][0] = __float_as_uint(f2tf(Qg[r_lo * 64 + kk * 8 + tig]     * scale));
        qa[kk][1] = __float_as_uint(f2tf(Qg[r_hi * 64 + kk * 8 + tig]     * scale));
        qa[kk][2] = __float_as_uint(f2tf(Qg[r_lo * 64 + kk * 8 + tig + 4] * scale));
        qa[kk][3] = __float_as_uint(f2tf(Qg[r_hi * 64 + kk * 8 + tig + 4] * scale));
    }
    __syncthreads();
    float ok_lo = mrow[r_lo] ? 1.f : 0.f;
    float ok_hi = mrow[r_hi] ? 1.f : 0.f;

    float o[8][4];
    #pragma unroll
    for (int nt = 0; nt < 8; nt++) { o[nt][0]=0.f; o[nt][1]=0.f; o[nt][2]=0.f; o[nt][3]=0.f; }
    float m0 = -1e30f, m1 = -1e30f, l0 = 0.f, l1 = 0.f;

    for (int kt = 0; kt < N_ / 64; kt++) {
        __syncthreads();
        const float* kg = Kg + kt * 4096;
        const float* vg = Vg + kt * 4096;
        for (int idx = t; idx < 1024; idx += 128) {
            int r = idx >> 4, c4 = (idx & 15) * 4;
            float4 kv = *(const float4*)&kg[r * 64 + c4];
            Ks[r * 68 + c4 + 0] = f2tf(kv.x); Ks[r * 68 + c4 + 1] = f2tf(kv.y);
            Ks[r * 68 + c4 + 2] = f2tf(kv.z); Ks[r * 68 + c4 + 3] = f2tf(kv.w);
            float4 vv = *(const float4*)&vg[r * 64 + c4];
            Vs[r * 72 + c4 + 0] = f2tf(vv.x); Vs[r * 72 + c4 + 1] = f2tf(vv.y);
            Vs[r * 72 + c4 + 2] = f2tf(vv.z); Vs[r * 72 + c4 + 3] = f2tf(vv.w);
        }
        __syncthreads();

        // ---- S = (Q/32) K^T : 8 k-steps x 8 n-tiles of m16n8k8 ----
        float s[8][4];
        #pragma unroll
        for (int nt = 0; nt < 8; nt++) { s[nt][0]=0.f; s[nt][1]=0.f; s[nt][2]=0.f; s[nt][3]=0.f; }
        #pragma unroll
        for (int kk = 0; kk < 8; kk++) {
            #pragma unroll
            for (int nt = 0; nt < 8; nt++) {
                uint32_t b0 = __float_as_uint(Ks[(nt * 8 + g) * 68 + kk * 8 + tig]);
                uint32_t b1 = __float_as_uint(Ks[(nt * 8 + g) * 68 + kk * 8 + tig + 4]);
                mma_tf32(s[nt], qa[kk][0], qa[kk][1], qa[kk][2], qa[kk][3], b0, b1);
            }
        }

        // ---- mask + online softmax on fragment layout ----
        float mt0 = -1e30f, mt1 = -1e30f;
        #pragma unroll
        for (int nt = 0; nt < 8; nt++) {
            s[nt][0] *= ok_lo; s[nt][1] *= ok_lo;
            s[nt][2] *= ok_hi; s[nt][3] *= ok_hi;
            mt0 = fmaxf(mt0, fmaxf(s[nt][0], s[nt][1]));
            mt1 = fmaxf(mt1, fmaxf(s[nt][2], s[nt][3]));
        }
        mt0 = fmaxf(mt0, __shfl_xor_sync(0xffffffffu, mt0, 1));
        mt0 = fmaxf(mt0, __shfl_xor_sync(0xffffffffu, mt0, 2));
        mt1 = fmaxf(mt1, __shfl_xor_sync(0xffffffffu, mt1, 1));
        mt1 = fmaxf(mt1, __shfl_xor_sync(0xffffffffu, mt1, 2));
        float mn0 = fmaxf(m0, mt0), mn1 = fmaxf(m1, mt1);
        float fac0 = __expf(m0 - mn0), fac1 = __expf(m1 - mn1);

        __syncwarp();   // prior PV reads of Ps done before overwriting
        float ps0 = 0.f, ps1 = 0.f;
        #pragma unroll
        for (int nt = 0; nt < 8; nt++) {
            float p00 = __expf(s[nt][0] - mn0), p01 = __expf(s[nt][1] - mn0);
            float p10 = __expf(s[nt][2] - mn1), p11 = __expf(s[nt][3] - mn1);
            ps0 += p00 + p01; ps1 += p10 + p11;
            Ps[r_lo * 68 + nt * 8 + 2 * tig]     = f2tf(p00);
            Ps[r_lo * 68 + nt * 8 + 2 * tig + 1] = f2tf(p01);
            Ps[r_hi * 68 + nt * 8 + 2 * tig]     = f2tf(p10);
            Ps[r_hi * 68 + nt * 8 + 2 * tig + 1] = f2tf(p11);
            // rescale running O
            o[nt][0] *= fac0; o[nt][1] *= fac0;
            o[nt][2] *= fac1; o[nt][3] *= fac1;
        }
        ps0 += __shfl_xor_sync(0xffffffffu, ps0, 1);
        ps0 += __shfl_xor_sync(0xffffffffu, ps0, 2);
        ps1 += __shfl_xor_sync(0xffffffffu, ps1, 1);
        ps1 += __shfl_xor_sync(0xffffffffu, ps1, 2);
        l0 = l0 * fac0 + ps0; m0 = mn0;
        l1 = l1 * fac1 + ps1; m1 = mn1;
        __syncwarp();   // P visible to all lanes of this warp

        // ---- O += P @ V ----
        #pragma unroll
        for (int kk = 0; kk < 8; kk++) {
            uint32_t a0 = __float_as_uint(Ps[r_lo * 68 + kk * 8 + tig]);
            uint32_t a1 = __float_as_uint(Ps[r_hi * 68 + kk * 8 + tig]);
            uint32_t a2 = __float_as_uint(Ps[r_lo * 68 + kk * 8 + tig + 4]);
            uint32_t a3 = __float_as_uint(Ps[r_hi * 68 + kk * 8 + tig + 4]);
            #pragma unroll
            for (int nt = 0; nt < 8; nt++) {
                uint32_t b0 = __float_as_uint(Vs[(kk * 8 + tig) * 72 + nt * 8 + g]);
                uint32_t b1 = __float_as_uint(Vs[(kk * 8 + tig + 4) * 72 + nt * 8 + g]);
                mma_tf32(o[nt], a0, a1, a2, a3, b0, b1);
            }
        }
    }

    float il0 = 1.f / l0, il1 = 1.f / l1;
    float* ob = g_attn + ((size_t)b * N_ + q0) * E_ + h * 64;
    #pragma unroll
    for (int nt = 0; nt < 8; nt++) {
        float2 lo = make_float2(o[nt][0] * il0, o[nt][1] * il0);
        float2 hi = make_float2(o[nt][2] * il1, o[nt][3] * il1);
        *(float2*)&ob[(size_t)r_lo * E_ + nt * 8 + 2 * tig] = lo;
        *(float2*)&ob[(size_t)r_hi * E_ + nt * 8 + 2 * tig] = hi;
    }
}

// ---------------------------------------------------------------------------
// Kernel 3: out = attn @ Wo^T with tf32 mma. Block 128 = 4 warps, 64x64 tile.
// out[m][n] = sum_k A[m][k] * Wo[n][k]  -> same row.col pattern as QK^T.
// ---------------------------------------------------------------------------
__global__ __launch_bounds__(128) void oproj_mma_kernel(
    const float* __restrict__ Wo, float* __restrict__ out)
{
    __shared__ __align__(16) float As[64 * 68];
    __shared__ __align__(16) float Ws[64 * 68];
    int rB = blockIdx.x * 64, cB = blockIdx.y * 64;
    int t = threadIdx.x;
    int w = t >> 5, lane = t & 31, g = lane >> 2, tig = lane & 3;
    int r_lo = w * 16 + g, r_hi = r_lo + 8;

    float o[8][4];
    #pragma unroll
    for (int nt = 0; nt < 8; nt++) { o[nt][0]=0.f; o[nt][1]=0.f; o[nt][2]=0.f; o[nt][3]=0.f; }

    for (int e0 = 0; e0 < E_; e0 += 64) {
        __syncthreads();
        for (int idx = t; idx < 1024; idx += 128) {
            int r = idx >> 4, c4 = (idx & 15) * 4;
            float4 av = *(const float4*)&g_attn[(size_t)(rB + r) * E_ + e0 + c4];
            As[r * 68 + c4 + 0] = f2tf(av.x); As[r * 68 + c4 + 1] = f2tf(av.y);
            As[r * 68 + c4 + 2] = f2tf(av.z); As[r * 68 + c4 + 3] = f2tf(av.w);
            float4 wv = *(const float4*)&Wo[(size_t)(cB + r) * E_ + e0 + c4];
            Ws[r * 68 + c4 + 0] = f2tf(wv.x); Ws[r * 68 + c4 + 1] = f2tf(wv.y);
            Ws[r * 68 + c4 + 2] = f2tf(wv.z); Ws[r * 68 + c4 + 3] = f2tf(wv.w);
        }
        __syncthreads();

        #pragma unroll
        for (int kk = 0; kk < 8; kk++) {
            uint32_t a0 = __float_as_uint(As[r_lo * 68 + kk * 8 + tig]);
            uint32_t a1 = __float_as_uint(As[r_hi * 68 + kk * 8 + tig]);
            uint32_t a2 = __float_as_uint(As[r_lo * 68 + kk * 8 + tig + 4]);
            uint32_t a3 = __float_as_uint(As[r_hi * 68 + kk * 8 + tig + 4]);
            #pragma unroll
            for (int nt = 0; nt < 8; nt++) {
                uint32_t b0 = __float_as_uint(Ws[(nt * 8 + g) * 68 + kk * 8 + tig]);
                uint32_t b1 = __float_as_uint(Ws[(nt * 8 + g) * 68 + kk * 8 + tig + 4]);
                mma_tf32(o[nt], a0, a1, a2, a3, b0, b1);
            }
        }
    }

    #pragma unroll
    for (int nt = 0; nt < 8; nt++) {
        float2 lo = make_float2(o[nt][0], o[nt][1]);
        float2 hi = make_float2(o[nt][2], o[nt][3]);
        *(float2*)&out[(size_t)(rB + r_lo) * E_ + cB + nt * 8 + 2 * tig] = lo;
        *(float2*)&out[(size_t)(rB + r_hi) * E_ + cB + nt * 8 + 2 * tig] = hi;
    }
}

// ---------------------------------------------------------------------------
extern "C" void kernel_launch(void* const* d_in, const int* in_sizes, int n_in,
                              void* d_out, int out_size)
{
    const float* q    = (const float*)d_in[0];
    const float* k    = (const float*)d_in[1];
    const float* v    = (const float*)d_in[2];
    const int*   mask = (const int*)  d_in[3];
    const float* Wq   = (const float*)d_in[4];
    const float* Wk   = (const float*)d_in[5];
    const float* Wv   = (const float*)d_in[6];
    const float* Wo   = (const float*)d_in[7];
    float* out = (float*)d_out;

    proj_kernel<<<dim3(N_ / 64, BH, 3), 256>>>(q, k, v, Wq, Wk, Wv);
    attn_mma_kernel<<<dim3(N_ / 64, BH), 128>>>(mask);
    oproj_mma_kernel<<<dim3(B_ * N_ / 64, E_ / 64), 128>>>(Wo, out);
}